// round 10
// baseline (speedup 1.0000x reference)
#include <cuda_runtime.h>

#define NN 64
#define CC 960
#define CS 240
#define HW 784
#define HW4 196              // float4s per (n,c) plane
#define NF4B (CC*HW4)        // float4s per batch image = 188160
#define PB 60                // pool blocks per batch  (8 warps * 2 planes * 60 = 960)
#define SB 735               // scale blocks per batch (188160 / 256)
#define GRP (PB+SB)          // 795
#define KAHEAD 6             // pool runs KAHEAD batches ahead of scale
#define GRID (KAHEAD*PB + NN*GRP)   // 360 + 50880 = 51240

// Scratch + sync state (zero-initialized; each run resets its own state).
__device__ float g_pooled[NN*CC];
__device__ float g_scale[NN*CC];
__device__ int   g_pcount[NN];
__device__ int   g_flag[NN];
__device__ int   g_sdone[NN];

__device__ __forceinline__ float warp_sum(float s) {
    #pragma unroll
    for (int d = 16; d; d >>= 1) s += __shfl_xor_sync(0xffffffffu, s, d);
    return s;
}

__global__ void __launch_bounds__(256) se_fused_kernel(
    const float* __restrict__ x, float* __restrict__ out,
    const float* __restrict__ w1, const float* __restrict__ b1,
    const float* __restrict__ w2, const float* __restrict__ b2)
{
    const unsigned bid  = blockIdx.x;
    const unsigned tid  = threadIdx.x;
    const unsigned wid  = tid >> 5;
    const unsigned lane = tid & 31u;

    // ---- decode work: pipelined order  pool(0..K-1), [pool(n+K)|scale(n)]*64
    int n, role, r = 0, s = 0;               // role 0 = pool, 1 = scale
    if (bid < KAHEAD * PB) { n = bid / PB; r = bid % PB; role = 0; }
    else {
        unsigned j = bid - KAHEAD * PB;
        unsigned g = j / GRP, t = j % GRP;
        if (t < PB) { n = g + KAHEAD; if (n >= NN) return; r = t; role = 0; }
        else        { n = g; s = t - PB; role = 1; }
    }

    if (role == 0) {
        // ================= POOL: this block covers 16 planes of batch n ======
        __shared__ int   s_old;
        {
            int p0 = r * 16 + wid * 2;                        // local plane pair
            const float4* P = reinterpret_cast<const float4*>(x)
                            + (size_t)(n * CC + p0) * HW4;
            float s0 = 0.f, s1 = 0.f;
            #pragma unroll 7
            for (int i = lane; i < HW4; i += 32) {
                float4 a = P[i];
                float4 b = P[i + HW4];
                s0 += (a.x + a.y) + (a.z + a.w);
                s1 += (b.x + b.y) + (b.z + b.w);
            }
            s0 = warp_sum(s0); s1 = warp_sum(s1);
            if (lane == 0) {
                __stcg(&g_pooled[n * CC + p0],     s0 * (1.0f / HW));
                __stcg(&g_pooled[n * CC + p0 + 1], s1 * (1.0f / HW));
                __threadfence();                  // publish before counter
            }
        }
        __syncthreads();
        if (tid == 0) s_old = atomicAdd(&g_pcount[n], 1);
        __syncthreads();
        if (s_old != PB - 1) return;              // not the elector

        // ============ ELECTED BLOCK: fc1 + relu + fc2 + hardsigmoid ==========
        __shared__ float sp[CC];
        __shared__ float sh[CS];
        for (int i = tid; i < CC; i += 256) sp[i] = __ldcg(&g_pooled[n * CC + i]);
        __syncthreads();

        for (int o = wid; o < CS; o += 8) {                   // 30 outputs/warp
            const float* wr = w1 + o * CC;
            float acc = 0.f;
            #pragma unroll 6
            for (int k = lane; k < CC; k += 32) acc += __ldg(&wr[k]) * sp[k];
            acc = warp_sum(acc);
            if (lane == 0) sh[o] = fmaxf(acc + __ldg(&b1[o]), 0.f);
        }
        __syncthreads();

        for (int c = wid; c < CC; c += 8) {                   // 120 outputs/warp
            const float* wr = w2 + c * CS;
            float acc = 0.f;
            #pragma unroll 4
            for (int k = lane; k < CS; k += 32) acc += __ldg(&wr[k]) * sh[k];
            acc = warp_sum(acc);
            if (lane == 0) {
                float g = __saturatef((acc + __ldg(&b2[c]) + 3.f) * (1.f / 6.f));
                __stcg(&g_scale[n * CC + c], g);
                __threadfence();                  // publish before flag
            }
        }
        __syncthreads();
        if (tid == 0) {
            g_pcount[n] = 0;                      // reset for next replay
            __threadfence();
            atomicExch(&g_flag[n], 1);            // release gate for batch n
        }
    } else {
        // ================= SCALE: 256 consecutive float4s of batch n =========
        __shared__ float sc[3];
        unsigned base = (unsigned)s * 256u;                   // batch-local f4
        unsigned nc0  = base / HW4;
        unsigned ncN  = (base + 255u) / HW4;                  // spans <= 3 planes

        if (tid == 0) {                                       // wait for gate
            volatile int* f = &g_flag[n];
            while (*f == 0) __nanosleep(128);
            __threadfence();
        }
        __syncthreads();

        if (tid <= ncN - nc0) sc[tid] = __ldcg(&g_scale[n * CC + nc0 + tid]);
        __syncthreads();

        unsigned i  = base + tid;
        float scv = sc[i / HW4 - nc0];
        size_t gi = (size_t)n * NF4B + i;
        float4 v = __ldcs(reinterpret_cast<const float4*>(x) + gi);
        v.x *= scv; v.y *= scv; v.z *= scv; v.w *= scv;
        __stcs(reinterpret_cast<float4*>(out) + gi, v);

        __syncthreads();
        if (tid == 0) {
            __threadfence();
            int old = atomicAdd(&g_sdone[n], 1);
            if (old == SB - 1) {                  // last consumer: reset state
                g_flag[n]  = 0;
                g_sdone[n] = 0;
            }
        }
    }
}

extern "C" void kernel_launch(void* const* d_in, const int* in_sizes, int n_in,
                              void* d_out, int out_size) {
    const float* x  = (const float*)d_in[0];
    const float* w1 = (const float*)d_in[1];
    const float* b1 = (const float*)d_in[2];
    const float* w2 = (const float*)d_in[3];
    const float* b2 = (const float*)d_in[4];
    se_fused_kernel<<<GRID, 256>>>(x, (float*)d_out, w1, b1, w2, b2);
}

// round 12
// speedup vs baseline: 8.5079x; 8.5079x over previous
#include <cuda_runtime.h>

#define NN 64
#define CC 960
#define CS 240
#define HW 784
#define HW4 196              // float4s per (n,c) plane
#define NF4B (CC*HW4)        // float4s per batch image = 188160
#define PB 60                // pool blocks per batch (8 warps * 2 planes * 60 = 960)
#define NBLK 47040           // scale blocks total = NN*NF4B/256

// Scratch (no device allocs). 16B-aligned: accessed through float4 casts.
__device__ __align__(16) float g_pooled[NN*CC];
__device__ __align__(16) float g_hidden[NN*CS];
__device__ int g_pcount[NN];     // zero-init, self-resetting each run

__device__ __forceinline__ float warp_sum(float s) {
    #pragma unroll
    for (int d = 16; d; d >>= 1) s += __shfl_xor_sync(0xffffffffu, s, d);
    return s;
}

// ---------------------------------------------------------------------------
// Kernel 1: pool + (elected last block per batch) fc1+relu.
// 60 blocks per batch; each covers 16 planes (8 warps x 2 planes).
// Elect tail has NO in-kernel consumers -> all 64 elect blocks run
// concurrently in the kernel's natural tail; kernel boundary is the sync.
// ---------------------------------------------------------------------------
__global__ void __launch_bounds__(256) pool_fc1_kernel(
    const float* __restrict__ x,
    const float* __restrict__ w1, const float* __restrict__ b1)
{
    const unsigned tid  = threadIdx.x;
    const unsigned wid  = tid >> 5;
    const unsigned lane = tid & 31u;
    const int n = blockIdx.x / PB;
    const int r = blockIdx.x % PB;

    // ---- pool 2 planes per warp ----
    {
        int p0 = r * 16 + wid * 2;
        const float4* P = reinterpret_cast<const float4*>(x)
                        + (size_t)(n * CC + p0) * HW4;
        float s0 = 0.f, s1 = 0.f;
        #pragma unroll 7
        for (int i = lane; i < HW4; i += 32) {
            float4 a = P[i];
            float4 b = P[i + HW4];
            s0 += (a.x + a.y) + (a.z + a.w);
            s1 += (b.x + b.y) + (b.z + b.w);
        }
        s0 = warp_sum(s0); s1 = warp_sum(s1);
        if (lane == 0) {
            __stcg(&g_pooled[n * CC + p0],     s0 * (1.0f / HW));
            __stcg(&g_pooled[n * CC + p0 + 1], s1 * (1.0f / HW));
        }
    }
    __shared__ int s_old;
    __threadfence();                                   // publish pooled
    __syncthreads();
    if (tid == 0) s_old = atomicAdd(&g_pcount[n], 1);
    __syncthreads();
    if (s_old != PB - 1) return;                       // not the elector

    // ---- elected: fc1 + relu for batch n ----
    __shared__ __align__(16) float sp[CC];
    for (int i = tid; i < CC; i += 256) sp[i] = __ldcg(&g_pooled[n * CC + i]);
    __syncthreads();

    for (int o = wid; o < CS; o += 8) {                // 30 outputs per warp
        const float4* wr = reinterpret_cast<const float4*>(w1) + (size_t)o * (CC / 4);
        const float4* pr = reinterpret_cast<const float4*>(sp);
        float acc = 0.f;
        #pragma unroll 8
        for (int i = lane; i < CC / 4; i += 32) {
            float4 a = __ldg(&wr[i]); float4 b = pr[i];
            acc += a.x * b.x + a.y * b.y + a.z * b.z + a.w * b.w;
        }
        acc = warp_sum(acc);
        if (lane == 0) g_hidden[n * CS + o] = fmaxf(acc + __ldg(&b1[o]), 0.f);
    }
    if (tid == 0) g_pcount[n] = 0;                     // reset for graph replay
}

// ---------------------------------------------------------------------------
// Kernel 2: fused fc2 + hardsigmoid + broadcast multiply. Forward order.
// Each block: 256 consecutive float4s (spans <= 3 planes). Warps 0..2
// recompute the <=3 gates (w2/g_hidden L2-resident), then stream-multiply.
// ---------------------------------------------------------------------------
__global__ void __launch_bounds__(256) scale_fused_kernel(
    const float* __restrict__ x, float* __restrict__ out,
    const float* __restrict__ w2, const float* __restrict__ b2)
{
    __shared__ float sc[3];
    const unsigned base = blockIdx.x * 256u;           // global float4 index
    const unsigned nc0  = base / HW4;
    const unsigned ncN  = (base + 255u) / HW4;         // inclusive
    const unsigned wid  = threadIdx.x >> 5, lane = threadIdx.x & 31u;

    if (wid <= ncN - nc0) {
        unsigned nc = nc0 + wid;
        unsigned n = nc / CC, c = nc % CC;
        const float4* wr = reinterpret_cast<const float4*>(w2) + (size_t)c * (CS / 4);
        const float4* hr = reinterpret_cast<const float4*>(g_hidden) + (size_t)n * (CS / 4);
        float s = 0.f;
        #pragma unroll 2
        for (int i = lane; i < CS / 4; i += 32) {      // 60 float4s
            float4 a = __ldg(&wr[i]); float4 b = __ldg(&hr[i]);
            s += a.x * b.x + a.y * b.y + a.z * b.z + a.w * b.w;
        }
        s = warp_sum(s);
        if (lane == 0) sc[wid] = __saturatef((s + __ldg(&b2[c]) + 3.f) * (1.f / 6.f));
    }
    __syncthreads();

    unsigned i = base + threadIdx.x;
    float s = sc[i / HW4 - nc0];
    float4 v = __ldcs(reinterpret_cast<const float4*>(x) + i);
    v.x *= s; v.y *= s; v.z *= s; v.w *= s;
    __stcs(reinterpret_cast<float4*>(out) + i, v);
}

// ---------------------------------------------------------------------------
extern "C" void kernel_launch(void* const* d_in, const int* in_sizes, int n_in,
                              void* d_out, int out_size) {
    const float* x  = (const float*)d_in[0];
    const float* w1 = (const float*)d_in[1];
    const float* b1 = (const float*)d_in[2];
    const float* w2 = (const float*)d_in[3];
    const float* b2 = (const float*)d_in[4];
    float* out = (float*)d_out;

    pool_fc1_kernel<<<NN * PB, 256>>>(x, w1, b1);          // 3840 blocks
    scale_fused_kernel<<<NBLK, 256>>>(x, out, w2, b2);     // 47040 blocks
}

// round 15
// speedup vs baseline: 14.4113x; 1.6939x over previous
#include <cuda_runtime.h>

#define NN 64
#define CC 960
#define CS 240
#define HW 784
#define HW4 196      // float4s per (n,c) plane
#define NC (NN*CC)   // 61440 planes
#define NBLK 47040   // scale blocks = NC*HW4/256

// Scratch (no device allocs). 16B-aligned: accessed through float4 casts.
__device__ __align__(16) float g_pooled[NC];
__device__ __align__(16) float g_hidden[NN*CS];
__device__ float g_scale[NC];

__device__ __forceinline__ float warp_sum(float s) {
    #pragma unroll
    for (int d = 16; d; d >>= 1) s += __shfl_xor_sync(0xffffffffu, s, d);
    return s;
}

// ---------------------------------------------------------------------------
// Kernel 1: global average pool. One warp per TWO (n,c) planes (R7: 38.3us).
// ---------------------------------------------------------------------------
__global__ void __launch_bounds__(256) pool_kernel(const float* __restrict__ x) {
    unsigned warp = (blockIdx.x * blockDim.x + threadIdx.x) >> 5;  // < NC/2
    unsigned lane = threadIdx.x & 31u;
    const float4* p = reinterpret_cast<const float4*>(x) + (size_t)warp * (2 * HW4);
    float s0 = 0.f, s1 = 0.f;
    #pragma unroll 7
    for (int i = lane; i < HW4; i += 32) {
        float4 a = p[i];
        float4 b = p[i + HW4];
        s0 += (a.x + a.y) + (a.z + a.w);
        s1 += (b.x + b.y) + (b.z + b.w);
    }
    s0 = warp_sum(s0); s1 = warp_sum(s1);
    if (lane == 0) {
        g_pooled[2 * warp]     = s0 * (1.0f / HW);
        g_pooled[2 * warp + 1] = s1 * (1.0f / HW);
    }
}

// ---------------------------------------------------------------------------
// Kernel 2: fc1 + relu. One warp per (n, o); 15360 warps / 1920 blocks.
// ---------------------------------------------------------------------------
__global__ void __launch_bounds__(256) fc1_kernel(
    const float* __restrict__ w1, const float* __restrict__ b1)
{
    unsigned w    = (blockIdx.x * blockDim.x + threadIdx.x) >> 5;   // < 15360
    unsigned lane = threadIdx.x & 31u;
    unsigned n = w / CS;
    unsigned o = w % CS;
    const float4* wr = reinterpret_cast<const float4*>(w1) + (size_t)o * (CC / 4);
    const float4* pr = reinterpret_cast<const float4*>(g_pooled) + (size_t)n * (CC / 4);
    float s = 0.f;
    #pragma unroll 8
    for (int i = lane; i < CC / 4; i += 32) {               // 240 float4s
        float4 a = wr[i], b = pr[i];
        s += a.x * b.x + a.y * b.y + a.z * b.z + a.w * b.w;
    }
    s = warp_sum(s);
    if (lane == 0) g_hidden[n * CS + o] = fmaxf(s + b1[o], 0.f);
}

// ---------------------------------------------------------------------------
// Kernel 3: fc2 + hardsigmoid. One warp per (n, c); 61440 warps / 7680 blocks.
// ---------------------------------------------------------------------------
__global__ void __launch_bounds__(256) fc2_kernel(
    const float* __restrict__ w2, const float* __restrict__ b2)
{
    unsigned w    = (blockIdx.x * blockDim.x + threadIdx.x) >> 5;   // < 61440
    unsigned lane = threadIdx.x & 31u;
    unsigned n = w / CC;
    unsigned c = w % CC;
    const float4* wr = reinterpret_cast<const float4*>(w2) + (size_t)c * (CS / 4);
    const float4* hr = reinterpret_cast<const float4*>(g_hidden) + (size_t)n * (CS / 4);
    float s = 0.f;
    #pragma unroll 2
    for (int i = lane; i < CS / 4; i += 32) {               // 60 float4s
        float4 a = wr[i], b = hr[i];
        s += a.x * b.x + a.y * b.y + a.z * b.z + a.w * b.w;
    }
    s = warp_sum(s);
    if (lane == 0) {
        g_scale[n * CC + c] = __saturatef((s + b2[c] + 3.f) * (1.f / 6.f));
    }
}

// ---------------------------------------------------------------------------
// Kernel 4: pure streaming scale, REVERSED block order. First-scheduled
// blocks read the tail of x — still L2-hot from pool's forward stream
// (fc1/fc2 touch only ~2MB unique in between). Body identical to R4's
// proven 56.9us kernel otherwise.
// ---------------------------------------------------------------------------
__global__ void __launch_bounds__(256) scale_kernel(
    const float* __restrict__ x, float* __restrict__ out)
{
    unsigned blk = (NBLK - 1u) - blockIdx.x;                // reversed
    unsigned i   = blk * 256u + threadIdx.x;                // < 12,042,240
    unsigned nc  = i / HW4;
    float sc = __ldg(&g_scale[nc]);
    float4 v = __ldcs(reinterpret_cast<const float4*>(x) + i);
    v.x *= sc; v.y *= sc; v.z *= sc; v.w *= sc;
    __stcs(reinterpret_cast<float4*>(out) + i, v);
}

// ---------------------------------------------------------------------------
extern "C" void kernel_launch(void* const* d_in, const int* in_sizes, int n_in,
                              void* d_out, int out_size) {
    const float* x  = (const float*)d_in[0];
    const float* w1 = (const float*)d_in[1];
    const float* b1 = (const float*)d_in[2];
    const float* w2 = (const float*)d_in[3];
    const float* b2 = (const float*)d_in[4];
    float* out = (float*)d_out;

    pool_kernel<<<(NC / 2 * 32) / 256, 256>>>(x);           // 3840 blocks
    fc1_kernel<<<(NN * CS * 32) / 256, 256>>>(w1, b1);      // 1920 blocks
    fc2_kernel<<<(NN * CC * 32) / 256, 256>>>(w2, b2);      // 7680 blocks
    scale_kernel<<<NBLK, 256>>>(x, out);                    // 47040 blocks
}

// round 16
// speedup vs baseline: 14.9432x; 1.0369x over previous
#include <cuda_runtime.h>

#define NN 64
#define CC 960
#define CS 240
#define HW 784
#define HW4 196      // float4s per (n,c) plane
#define NC (NN*CC)   // 61440 planes
#define NBLK 47040   // scale blocks = NC*HW4/256

// Scratch (no device allocs). 16B-aligned: accessed through float4 casts.
__device__ __align__(16) float g_pooled[NC];
__device__ __align__(16) float g_hidden[NN*CS];
__device__ float g_scale[NC];

__device__ __forceinline__ float warp_sum(float s) {
    #pragma unroll
    for (int d = 16; d; d >>= 1) s += __shfl_xor_sync(0xffffffffu, s, d);
    return s;
}
__device__ __forceinline__ void pdl_trigger() {
    asm volatile("griddepcontrol.launch_dependents;");
}
__device__ __forceinline__ void pdl_wait() {
    asm volatile("griddepcontrol.wait;" ::: "memory");
}

// ---------------------------------------------------------------------------
// Kernel 1: global average pool. One warp per FOUR (n,c) planes.
// 4 independent load streams/warp; one float4 store amortizes the epilogue.
// ---------------------------------------------------------------------------
__global__ void __launch_bounds__(256) pool_kernel(const float* __restrict__ x) {
    unsigned warp = (blockIdx.x * blockDim.x + threadIdx.x) >> 5;  // < NC/4
    unsigned lane = threadIdx.x & 31u;
    const float4* p = reinterpret_cast<const float4*>(x) + (size_t)warp * (4 * HW4);
    float s0 = 0.f, s1 = 0.f, s2 = 0.f, s3 = 0.f;
    #pragma unroll 3
    for (int i = lane; i < HW4; i += 32) {
        float4 a = p[i];
        float4 b = p[i + HW4];
        float4 c = p[i + 2 * HW4];
        float4 d = p[i + 3 * HW4];
        s0 += (a.x + a.y) + (a.z + a.w);
        s1 += (b.x + b.y) + (b.z + b.w);
        s2 += (c.x + c.y) + (c.z + c.w);
        s3 += (d.x + d.y) + (d.z + d.w);
    }
    s0 = warp_sum(s0); s1 = warp_sum(s1); s2 = warp_sum(s2); s3 = warp_sum(s3);
    if (lane == 0) {
        float4 r;
        r.x = s0 * (1.0f / HW); r.y = s1 * (1.0f / HW);
        r.z = s2 * (1.0f / HW); r.w = s3 * (1.0f / HW);
        reinterpret_cast<float4*>(g_pooled)[warp] = r;
    }
    pdl_trigger();                                      // writes above now visible to waiters
}

// ---------------------------------------------------------------------------
// Kernel 2: fc1 + relu. One warp per (n, o); 15360 warps / 1920 blocks.
// ---------------------------------------------------------------------------
__global__ void __launch_bounds__(256) fc1_kernel(
    const float* __restrict__ w1, const float* __restrict__ b1)
{
    unsigned w    = (blockIdx.x * blockDim.x + threadIdx.x) >> 5;   // < 15360
    unsigned lane = threadIdx.x & 31u;
    unsigned n = w / CS;
    unsigned o = w % CS;
    pdl_wait();                                         // g_pooled ready
    const float4* wr = reinterpret_cast<const float4*>(w1) + (size_t)o * (CC / 4);
    const float4* pr = reinterpret_cast<const float4*>(g_pooled) + (size_t)n * (CC / 4);
    float s = 0.f;
    #pragma unroll 8
    for (int i = lane; i < CC / 4; i += 32) {               // 240 float4s
        float4 a = wr[i], b = pr[i];
        s += a.x * b.x + a.y * b.y + a.z * b.z + a.w * b.w;
    }
    s = warp_sum(s);
    if (lane == 0) g_hidden[n * CS + o] = fmaxf(s + b1[o], 0.f);
    pdl_trigger();
}

// ---------------------------------------------------------------------------
// Kernel 3: fc2 + hardsigmoid. One warp per (n, c); 61440 warps / 7680 blocks.
// ---------------------------------------------------------------------------
__global__ void __launch_bounds__(256) fc2_kernel(
    const float* __restrict__ w2, const float* __restrict__ b2)
{
    unsigned w    = (blockIdx.x * blockDim.x + threadIdx.x) >> 5;   // < 61440
    unsigned lane = threadIdx.x & 31u;
    unsigned n = w / CC;
    unsigned c = w % CC;
    pdl_wait();                                         // g_hidden ready
    const float4* wr = reinterpret_cast<const float4*>(w2) + (size_t)c * (CS / 4);
    const float4* hr = reinterpret_cast<const float4*>(g_hidden) + (size_t)n * (CS / 4);
    float s = 0.f;
    #pragma unroll 2
    for (int i = lane; i < CS / 4; i += 32) {               // 60 float4s
        float4 a = wr[i], b = hr[i];
        s += a.x * b.x + a.y * b.y + a.z * b.z + a.w * b.w;
    }
    s = warp_sum(s);
    if (lane == 0) {
        g_scale[n * CC + c] = __saturatef((s + b2[c] + 3.f) * (1.f / 6.f));
    }
    pdl_trigger();
}

// ---------------------------------------------------------------------------
// Kernel 4: pure streaming scale. The x load issues BEFORE griddepcontrol.wait
// so the 386MB stream overlaps the tail of fc1/fc2; only the tiny gate read
// needs the dependency.
// ---------------------------------------------------------------------------
__global__ void __launch_bounds__(256) scale_kernel(
    const float* __restrict__ x, float* __restrict__ out)
{
    unsigned i  = blockIdx.x * 256u + threadIdx.x;          // < 12,042,240
    unsigned nc = i / HW4;
    float4 v = __ldcs(reinterpret_cast<const float4*>(x) + i);  // overlaps fc2
    pdl_wait();                                         // g_scale ready
    float sc = __ldg(&g_scale[nc]);
    v.x *= sc; v.y *= sc; v.z *= sc; v.w *= sc;
    __stcs(reinterpret_cast<float4*>(out) + i, v);
}

// ---------------------------------------------------------------------------
static void launch_pdl(const void* func, dim3 grid, dim3 block, void** args) {
    cudaLaunchConfig_t cfg = {};
    cfg.gridDim = grid; cfg.blockDim = block; cfg.stream = 0;
    cudaLaunchAttribute attr[1];
    attr[0].id = cudaLaunchAttributeProgrammaticStreamSerialization;
    attr[0].val.programmaticStreamSerializationAllowed = 1;
    cfg.attrs = attr; cfg.numAttrs = 1;
    cudaLaunchKernelExC(&cfg, func, args);
}

extern "C" void kernel_launch(void* const* d_in, const int* in_sizes, int n_in,
                              void* d_out, int out_size) {
    const float* x  = (const float*)d_in[0];
    const float* w1 = (const float*)d_in[1];
    const float* b1 = (const float*)d_in[2];
    const float* w2 = (const float*)d_in[3];
    const float* b2 = (const float*)d_in[4];
    float* out = (float*)d_out;

    pool_kernel<<<(NC / 4 * 32) / 256, 256>>>(x);           // 1920 blocks

    void* a1[] = { (void*)&w1, (void*)&b1 };
    launch_pdl((const void*)fc1_kernel, dim3((NN * CS * 32) / 256), dim3(256), a1);

    void* a2[] = { (void*)&w2, (void*)&b2 };
    launch_pdl((const void*)fc2_kernel, dim3((NN * CC * 32) / 256), dim3(256), a2);

    void* a3[] = { (void*)&x, (void*)&out };
    launch_pdl((const void*)scale_kernel, dim3(NBLK), dim3(256), a3);
}